// round 2
// baseline (speedup 1.0000x reference)
#include <cuda_runtime.h>
#include <cuda_bf16.h>
#include <mma.h>
#include <math.h>

using namespace nvcuda;

// Problem constants
#define BATCH 4
#define SEQ   1024
#define DIM   4096
#define NH    32
#define NKV   8
#define HD    128
#define NTOK  (BATCH*SEQ)           // 4096 tokens
#define SCALE 0.08838834764831845f  // 1/sqrt(128)

// ---------------- scratch (device globals; no allocation allowed) ----------------
__device__ float g_Q[(size_t)NTOK * DIM];          // 64 MB  [b,s,h,d]
__device__ float g_K[(size_t)NTOK * NKV * HD];     // 16 MB  [b,s,kv,d]
__device__ float g_V[(size_t)NTOK * NKV * HD];     // 16 MB
__device__ float g_S[(size_t)BATCH * NH * SEQ * SEQ]; // 512 MB scores/probs
__device__ float g_A[(size_t)NTOK * DIM];          // 64 MB attn output

// ---------------- generic 64x64 TF32 wmma GEMM block ----------------
// C[M,N] = A @ B   (BT=false: B is [K,N] row-major)
//        = A @ B^T (BT=true:  B is [N,K] row-major)
// 128 threads (4 warps, 2x2), each warp owns a 32x32 output tile (2x2 wmma 16x16).
template<bool BT>
__device__ __forceinline__ void gemm_block(const float* __restrict__ A, int lda,
                                           const float* __restrict__ B, int ldb,
                                           float* __restrict__ C, int ldc, int K)
{
    __shared__ float sA[64 * 36];   // [row][k], stride 36
    __shared__ float sB[64 * 36];   // BT: [n][k] stride 36; !BT: [k][n] stride 68 (fits: 32*68 <= 64*36)

    const int tid  = threadIdx.x;
    const int warp = tid >> 5;
    const int wm   = (warp >> 1) * 32;
    const int wn   = (warp & 1) * 32;
    const int bm   = blockIdx.y * 64;
    const int bn   = blockIdx.x * 64;

    wmma::fragment<wmma::accumulator, 16, 16, 8, float> acc[2][2];
#pragma unroll
    for (int i = 0; i < 2; i++)
#pragma unroll
        for (int j = 0; j < 2; j++) wmma::fill_fragment(acc[i][j], 0.0f);

    for (int k0 = 0; k0 < K; k0 += 32) {
        // load A tile 64x32 (512 float4, 128 threads -> 4 each)
        for (int i = tid; i < 512; i += 128) {
            int r = i >> 3, c4 = i & 7;
            *(float4*)&sA[r * 36 + c4 * 4] =
                *(const float4*)&A[(size_t)(bm + r) * lda + k0 + c4 * 4];
        }
        if (BT) {
            // sB[n][k] = B[(bn+n)*ldb + k0+k]
            for (int i = tid; i < 512; i += 128) {
                int n = i >> 3, c4 = i & 7;
                *(float4*)&sB[n * 36 + c4 * 4] =
                    *(const float4*)&B[(size_t)(bn + n) * ldb + k0 + c4 * 4];
            }
        } else {
            // sB[k][n] = B[(k0+k)*ldb + bn+n], stride 68
            for (int i = tid; i < 512; i += 128) {
                int r = i >> 4, c4 = i & 15;
                *(float4*)&sB[r * 68 + c4 * 4] =
                    *(const float4*)&B[(size_t)(k0 + r) * ldb + bn + c4 * 4];
            }
        }
        __syncthreads();

#pragma unroll
        for (int kk = 0; kk < 32; kk += 8) {
            wmma::fragment<wmma::matrix_a, 16, 16, 8, wmma::precision::tf32, wmma::row_major> af[2];
#pragma unroll
            for (int i = 0; i < 2; i++) {
                wmma::load_matrix_sync(af[i], &sA[(wm + i * 16) * 36 + kk], 36);
#pragma unroll
                for (int t = 0; t < af[i].num_elements; t++)
                    af[i].x[t] = wmma::__float_to_tf32(af[i].x[t]);
            }
            if (BT) {
                wmma::fragment<wmma::matrix_b, 16, 16, 8, wmma::precision::tf32, wmma::col_major> bf[2];
#pragma unroll
                for (int j = 0; j < 2; j++) {
                    wmma::load_matrix_sync(bf[j], &sB[(wn + j * 16) * 36 + kk], 36);
#pragma unroll
                    for (int t = 0; t < bf[j].num_elements; t++)
                        bf[j].x[t] = wmma::__float_to_tf32(bf[j].x[t]);
                }
#pragma unroll
                for (int i = 0; i < 2; i++)
#pragma unroll
                    for (int j = 0; j < 2; j++)
                        wmma::mma_sync(acc[i][j], af[i], bf[j], acc[i][j]);
            } else {
                wmma::fragment<wmma::matrix_b, 16, 16, 8, wmma::precision::tf32, wmma::row_major> bf[2];
#pragma unroll
                for (int j = 0; j < 2; j++) {
                    wmma::load_matrix_sync(bf[j], &sB[kk * 68 + wn + j * 16], 68);
#pragma unroll
                    for (int t = 0; t < bf[j].num_elements; t++)
                        bf[j].x[t] = wmma::__float_to_tf32(bf[j].x[t]);
                }
#pragma unroll
                for (int i = 0; i < 2; i++)
#pragma unroll
                    for (int j = 0; j < 2; j++)
                        wmma::mma_sync(acc[i][j], af[i], bf[j], acc[i][j]);
            }
        }
        __syncthreads();
    }

#pragma unroll
    for (int i = 0; i < 2; i++)
#pragma unroll
        for (int j = 0; j < 2; j++)
            wmma::store_matrix_sync(&C[(size_t)(bm + wm + i * 16) * ldc + bn + wn + j * 16],
                                    acc[i][j], ldc, wmma::mem_row_major);
}

// ---------------- projection kernels ----------------
__global__ void k_gemm_q(const float* __restrict__ x, const float* __restrict__ w) {
    gemm_block<false>(x, DIM, w, DIM, g_Q, DIM, DIM);
}
__global__ void k_gemm_k(const float* __restrict__ x, const float* __restrict__ w) {
    gemm_block<false>(x, DIM, w, NKV * HD, g_K, NKV * HD, DIM);
}
__global__ void k_gemm_v(const float* __restrict__ x, const float* __restrict__ w) {
    gemm_block<false>(x, DIM, w, NKV * HD, g_V, NKV * HD, DIM);
}
__global__ void k_gemm_o(const float* __restrict__ w, float* __restrict__ out) {
    gemm_block<false>(g_A, DIM, w, DIM, out, DIM, DIM);
}

// ---------------- RoPE ----------------
__device__ __forceinline__ void rope_apply(float* t, const float* __restrict__ cs,
                                           const float* __restrict__ sn, int nh)
{
    int idx = blockIdx.x * 256 + threadIdx.x;   // over B*S*nh*64
    int i   = idx & 63;
    int th  = idx >> 6;                          // token-head index
    int s   = (th / nh) & (SEQ - 1);
    float c  = cs[s * 64 + i];
    float si = sn[s * 64 + i];
    size_t off = (size_t)th * HD + 2 * i;
    float v0 = t[off], v1 = t[off + 1];
    t[off]     = v0 * c - v1 * si;
    t[off + 1] = v0 * si + v1 * c;
}
__global__ void k_rope_q(const float* __restrict__ cs, const float* __restrict__ sn) {
    rope_apply(g_Q, cs, sn, NH);
}
__global__ void k_rope_k(const float* __restrict__ cs, const float* __restrict__ sn) {
    rope_apply(g_K, cs, sn, NKV);
}

// ---------------- attention scores: S[z] = Q_bh @ K_bkv^T ----------------
__global__ void k_score() {
    int z = blockIdx.z;              // b*NH + h
    int b = z >> 5, h = z & 31, kvh = h >> 2;
    const float* A = g_Q + (size_t)b * SEQ * DIM + h * HD;       // lda DIM
    const float* B = g_K + (size_t)b * SEQ * (NKV * HD) + kvh * HD; // ldb NKV*HD
    float*       C = g_S + (size_t)z * SEQ * SEQ;                 // ldc SEQ
    gemm_block<true>(A, DIM, B, NKV * HD, C, SEQ, HD);
}

// ---------------- softmax over rows of g_S (scale applied here) ----------------
__global__ void k_softmax() {
    size_t row = blockIdx.x;
    float* p = g_S + row * SEQ;
    int tid = threadIdx.x;       // 128 threads, 8 elems each
    int lane = tid & 31, warp = tid >> 5;

    float v[8];
    float m = -1e30f;
#pragma unroll
    for (int i = 0; i < 8; i++) { v[i] = p[tid + i * 128] * SCALE; m = fmaxf(m, v[i]); }
#pragma unroll
    for (int o = 16; o; o >>= 1) m = fmaxf(m, __shfl_xor_sync(0xffffffffu, m, o));
    __shared__ float sm[4];
    if (!lane) sm[warp] = m;
    __syncthreads();
    m = fmaxf(fmaxf(sm[0], sm[1]), fmaxf(sm[2], sm[3]));

    float sum = 0.0f;
#pragma unroll
    for (int i = 0; i < 8; i++) { v[i] = expf(v[i] - m); sum += v[i]; }
#pragma unroll
    for (int o = 16; o; o >>= 1) sum += __shfl_xor_sync(0xffffffffu, sum, o);
    __shared__ float ss[4];
    if (!lane) ss[warp] = sum;
    __syncthreads();
    sum = ss[0] + ss[1] + ss[2] + ss[3];

    float inv = 1.0f / sum;
#pragma unroll
    for (int i = 0; i < 8; i++) p[tid + i * 128] = v[i] * inv;
}

// ---------------- P @ V ----------------
__global__ void k_pv() {
    int z = blockIdx.z;
    int b = z >> 5, h = z & 31, kvh = h >> 2;
    const float* A = g_S + (size_t)z * SEQ * SEQ;                   // lda SEQ
    const float* B = g_V + (size_t)b * SEQ * (NKV * HD) + kvh * HD; // ldb NKV*HD
    float*       C = g_A + (size_t)b * SEQ * DIM + h * HD;          // ldc DIM
    gemm_block<false>(A, SEQ, B, NKV * HD, C, DIM, SEQ);
}

// ---------------- launch ----------------
extern "C" void kernel_launch(void* const* d_in, const int* in_sizes, int n_in,
                              void* d_out, int out_size)
{
    const float* x  = (const float*)d_in[0];
    const float* fc = (const float*)d_in[1];
    const float* fs = (const float*)d_in[2];
    const float* wq = (const float*)d_in[3];
    const float* wk = (const float*)d_in[4];
    const float* wv = (const float*)d_in[5];
    const float* wo = (const float*)d_in[6];
    float* out = (float*)d_out;

    dim3 blk(128);

    // QKV projections
    k_gemm_q<<<dim3(DIM / 64, NTOK / 64), blk>>>(x, wq);
    k_gemm_k<<<dim3((NKV * HD) / 64, NTOK / 64), blk>>>(x, wk);
    k_gemm_v<<<dim3((NKV * HD) / 64, NTOK / 64), blk>>>(x, wv);

    // RoPE
    k_rope_q<<<(BATCH * SEQ * NH * 64) / 256, 256>>>(fc, fs);
    k_rope_k<<<(BATCH * SEQ * NKV * 64) / 256, 256>>>(fc, fs);

    // scores, softmax, PV
    k_score<<<dim3(SEQ / 64, SEQ / 64, BATCH * NH), blk>>>();
    k_softmax<<<BATCH * NH * SEQ, 128>>>();
    k_pv<<<dim3(HD / 64, SEQ / 64, BATCH * NH), blk>>>();

    // output projection
    k_gemm_o<<<dim3(DIM / 64, DIM / 64), blk>>>(wo, out);
}

// round 3
// speedup vs baseline: 1.5543x; 1.5543x over previous
#include <cuda_runtime.h>
#include <cuda_bf16.h>
#include <cuda_pipeline.h>
#include <mma.h>
#include <math.h>

using namespace nvcuda;

#define BATCH 4
#define SEQ   1024
#define DIM   4096
#define NH    32
#define NKV   8
#define HD    128
#define NTOK  (BATCH*SEQ)
#define SCALE 0.08838834764831845f

// tiles
#define BM 128
#define BN 128
#define BK 16
#define SA_STRIDE 20    // 16 + 4 pad (floats); 80B row, 16B divisible
#define SB_STRIDE 20    // BT case [n][k]
#define SBN_STRIDE 132  // !BT case [k][n]; 528B row, 16B divisible

// ---------------- scratch ----------------
__device__ float g_Q[(size_t)NTOK * DIM];
__device__ float g_K[(size_t)NTOK * NKV * HD];
__device__ float g_V[(size_t)NTOK * NKV * HD];
__device__ float g_S[(size_t)BATCH * NH * SEQ * SEQ];
__device__ float g_A[(size_t)NTOK * DIM];

// ---------------- 128x128x16 TF32 wmma GEMM, cp.async double-buffered ----------
// C[M,N] = A @ B   (BT=false: B is [K,N] row-major)
//        = A @ B^T (BT=true:  B is [N,K] row-major)
// 256 threads = 8 warps in 4(m) x 2(n); warp tile 32x64 = 2x4 wmma 16x16x8.
template<bool BT>
__device__ __forceinline__ void gemm_block(const float* __restrict__ A, int lda,
                                           const float* __restrict__ B, int ldb,
                                           float* __restrict__ C, int ldc, int K)
{
    __shared__ float sA[2][BM * SA_STRIDE];       // 2 x 10KB
    __shared__ float sB[2][BM * SB_STRIDE];       // 2 x 10KB (covers both layouts)

    const int tid  = threadIdx.x;
    const int warp = tid >> 5;
    const int wm   = (warp >> 1) * 32;
    const int wn   = (warp & 1) * 64;
    const int bm   = blockIdx.y * BM;
    const int bn   = blockIdx.x * BN;

    wmma::fragment<wmma::accumulator, 16, 16, 8, float> acc[2][4];
#pragma unroll
    for (int i = 0; i < 2; i++)
#pragma unroll
        for (int j = 0; j < 4; j++) wmma::fill_fragment(acc[i][j], 0.0f);

    // ---- async tile loaders (each: 512 float4, 256 threads x 2) ----
    auto load_tile = [&](int st, int k0) {
#pragma unroll
        for (int l = 0; l < 2; l++) {
            int idx = tid + l * 256;
            // A: 128 rows x 16 cols
            {
                int r = idx >> 2, c4 = idx & 3;
                __pipeline_memcpy_async(&sA[st][r * SA_STRIDE + c4 * 4],
                                        &A[(size_t)(bm + r) * lda + k0 + c4 * 4], 16);
            }
            if (BT) {
                int n = idx >> 2, c4 = idx & 3;
                __pipeline_memcpy_async(&sB[st][n * SB_STRIDE + c4 * 4],
                                        &B[(size_t)(bn + n) * ldb + k0 + c4 * 4], 16);
            } else {
                int r = idx >> 5, c4 = idx & 31;
                __pipeline_memcpy_async(&sB[st][r * SBN_STRIDE + c4 * 4],
                                        &B[(size_t)(k0 + r) * ldb + bn + c4 * 4], 16);
            }
        }
    };

    const int nt = K / BK;
    load_tile(0, 0);
    __pipeline_commit();

    for (int t = 0; t < nt; t++) {
        if (t + 1 < nt) {
            load_tile((t + 1) & 1, (t + 1) * BK);
            __pipeline_commit();
            __pipeline_wait_prior(1);
        } else {
            __pipeline_wait_prior(0);
        }
        __syncthreads();

        const int st = t & 1;
#pragma unroll
        for (int kk = 0; kk < BK; kk += 8) {
            wmma::fragment<wmma::matrix_a, 16, 16, 8, wmma::precision::tf32, wmma::row_major> af[2];
#pragma unroll
            for (int i = 0; i < 2; i++) {
                wmma::load_matrix_sync(af[i], &sA[st][(wm + i * 16) * SA_STRIDE + kk], SA_STRIDE);
#pragma unroll
                for (int e = 0; e < af[i].num_elements; e++)
                    af[i].x[e] = wmma::__float_to_tf32(af[i].x[e]);
            }
            if (BT) {
                wmma::fragment<wmma::matrix_b, 16, 16, 8, wmma::precision::tf32, wmma::col_major> bf[4];
#pragma unroll
                for (int j = 0; j < 4; j++) {
                    wmma::load_matrix_sync(bf[j], &sB[st][(wn + j * 16) * SB_STRIDE + kk], SB_STRIDE);
#pragma unroll
                    for (int e = 0; e < bf[j].num_elements; e++)
                        bf[j].x[e] = wmma::__float_to_tf32(bf[j].x[e]);
                }
#pragma unroll
                for (int i = 0; i < 2; i++)
#pragma unroll
                    for (int j = 0; j < 4; j++)
                        wmma::mma_sync(acc[i][j], af[i], bf[j], acc[i][j]);
            } else {
                wmma::fragment<wmma::matrix_b, 16, 16, 8, wmma::precision::tf32, wmma::row_major> bf[4];
#pragma unroll
                for (int j = 0; j < 4; j++) {
                    wmma::load_matrix_sync(bf[j], &sB[st][kk * SBN_STRIDE + wn + j * 16], SBN_STRIDE);
#pragma unroll
                    for (int e = 0; e < bf[j].num_elements; e++)
                        bf[j].x[e] = wmma::__float_to_tf32(bf[j].x[e]);
                }
#pragma unroll
                for (int i = 0; i < 2; i++)
#pragma unroll
                    for (int j = 0; j < 4; j++)
                        wmma::mma_sync(acc[i][j], af[i], bf[j], acc[i][j]);
            }
        }
        __syncthreads();
    }

#pragma unroll
    for (int i = 0; i < 2; i++)
#pragma unroll
        for (int j = 0; j < 4; j++)
            wmma::store_matrix_sync(&C[(size_t)(bm + wm + i * 16) * ldc + bn + wn + j * 16],
                                    acc[i][j], ldc, wmma::mem_row_major);
}

// ---------------- projection kernels ----------------
__global__ void __launch_bounds__(256, 2) k_gemm_q(const float* __restrict__ x, const float* __restrict__ w) {
    gemm_block<false>(x, DIM, w, DIM, g_Q, DIM, DIM);
}
__global__ void __launch_bounds__(256, 2) k_gemm_k(const float* __restrict__ x, const float* __restrict__ w) {
    gemm_block<false>(x, DIM, w, NKV * HD, g_K, NKV * HD, DIM);
}
__global__ void __launch_bounds__(256, 2) k_gemm_v(const float* __restrict__ x, const float* __restrict__ w) {
    gemm_block<false>(x, DIM, w, NKV * HD, g_V, NKV * HD, DIM);
}
__global__ void __launch_bounds__(256, 2) k_gemm_o(const float* __restrict__ w, float* __restrict__ out) {
    gemm_block<false>(g_A, DIM, w, DIM, out, DIM, DIM);
}

// ---------------- RoPE ----------------
__device__ __forceinline__ void rope_apply(float* t, const float* __restrict__ cs,
                                           const float* __restrict__ sn, int nh)
{
    int idx = blockIdx.x * 256 + threadIdx.x;
    int i   = idx & 63;
    int th  = idx >> 6;
    int s   = (th / nh) & (SEQ - 1);
    float c  = cs[s * 64 + i];
    float si = sn[s * 64 + i];
    size_t off = (size_t)th * HD + 2 * i;
    float v0 = t[off], v1 = t[off + 1];
    t[off]     = v0 * c - v1 * si;
    t[off + 1] = v0 * si + v1 * c;
}
__global__ void k_rope_q(const float* __restrict__ cs, const float* __restrict__ sn) {
    rope_apply(g_Q, cs, sn, NH);
}
__global__ void k_rope_k(const float* __restrict__ cs, const float* __restrict__ sn) {
    rope_apply(g_K, cs, sn, NKV);
}

// ---------------- attention scores: S[z] = Q_bh @ K_bkv^T ----------------
__global__ void __launch_bounds__(256, 2) k_score() {
    int z = blockIdx.z;
    int b = z >> 5, h = z & 31, kvh = h >> 2;
    const float* A = g_Q + (size_t)b * SEQ * DIM + h * HD;
    const float* B = g_K + (size_t)b * SEQ * (NKV * HD) + kvh * HD;
    float*       C = g_S + (size_t)z * SEQ * SEQ;
    gemm_block<true>(A, DIM, B, NKV * HD, C, SEQ, HD);
}

// ---------------- softmax ----------------
__global__ void k_softmax() {
    size_t row = blockIdx.x;
    float* p = g_S + row * SEQ;
    int tid = threadIdx.x;
    int lane = tid & 31, warp = tid >> 5;

    float v[8];
    float m = -1e30f;
#pragma unroll
    for (int i = 0; i < 8; i++) { v[i] = p[tid + i * 128] * SCALE; m = fmaxf(m, v[i]); }
#pragma unroll
    for (int o = 16; o; o >>= 1) m = fmaxf(m, __shfl_xor_sync(0xffffffffu, m, o));
    __shared__ float sm[4];
    if (!lane) sm[warp] = m;
    __syncthreads();
    m = fmaxf(fmaxf(sm[0], sm[1]), fmaxf(sm[2], sm[3]));

    float sum = 0.0f;
#pragma unroll
    for (int i = 0; i < 8; i++) { v[i] = __expf(v[i] - m); sum += v[i]; }
#pragma unroll
    for (int o = 16; o; o >>= 1) sum += __shfl_xor_sync(0xffffffffu, sum, o);
    __shared__ float ss[4];
    if (!lane) ss[warp] = sum;
    __syncthreads();
    sum = ss[0] + ss[1] + ss[2] + ss[3];

    float inv = 1.0f / sum;
#pragma unroll
    for (int i = 0; i < 8; i++) p[tid + i * 128] = v[i] * inv;
}

// ---------------- P @ V ----------------
__global__ void __launch_bounds__(256, 2) k_pv() {
    int z = blockIdx.z;
    int b = z >> 5, h = z & 31, kvh = h >> 2;
    const float* A = g_S + (size_t)z * SEQ * SEQ;
    const float* B = g_V + (size_t)b * SEQ * (NKV * HD) + kvh * HD;
    float*       C = g_A + (size_t)b * SEQ * DIM + h * HD;
    gemm_block<false>(A, SEQ, B, NKV * HD, C, DIM, SEQ);
}

// ---------------- launch ----------------
extern "C" void kernel_launch(void* const* d_in, const int* in_sizes, int n_in,
                              void* d_out, int out_size)
{
    const float* x  = (const float*)d_in[0];
    const float* fc = (const float*)d_in[1];
    const float* fs = (const float*)d_in[2];
    const float* wq = (const float*)d_in[3];
    const float* wk = (const float*)d_in[4];
    const float* wv = (const float*)d_in[5];
    const float* wo = (const float*)d_in[6];
    float* out = (float*)d_out;

    dim3 blk(256);

    k_gemm_q<<<dim3(DIM / BN, NTOK / BM), blk>>>(x, wq);
    k_gemm_k<<<dim3((NKV * HD) / BN, NTOK / BM), blk>>>(x, wk);
    k_gemm_v<<<dim3((NKV * HD) / BN, NTOK / BM), blk>>>(x, wv);

    k_rope_q<<<(BATCH * SEQ * NH * 64) / 256, 256>>>(fc, fs);
    k_rope_k<<<(BATCH * SEQ * NKV * 64) / 256, 256>>>(fc, fs);

    k_score<<<dim3(SEQ / BN, SEQ / BM, BATCH * NH), blk>>>();
    k_softmax<<<BATCH * NH * SEQ, 128>>>();
    k_pv<<<dim3(HD / BN, SEQ / BM, BATCH * NH), blk>>>();

    k_gemm_o<<<dim3(DIM / BN, DIM / BM), blk>>>(wo, out);
}